// round 1
// baseline (speedup 1.0000x reference)
#include <cuda_runtime.h>

#define NN  80000
#define NE  1280000
#define NGR 8

// ---- scratch (device globals; no runtime allocation) ----
__device__ float    g_bufT[NN * 64];     // transformed features (message source)
__device__ float    g_bufA[NN * 64];     // aggregation target
__device__ unsigned g_mx1[NGR * 32];     // encoded per-graph max, stage 1
__device__ unsigned g_mx2[NGR * 64];     // encoded per-graph max, stage 2
__device__ float    g_tT3[NGR * 64];     // pooled1 @ W3  (GCN3 message table)
__device__ float    g_tT5[NGR * 20];     // pooled2 @ W5  (GCN5 message table)

// ordered-uint encoding of float for atomicMax (handles mixed signs)
__device__ __forceinline__ unsigned encf(float f) {
    unsigned u = __float_as_uint(f);
    return (u & 0x80000000u) ? ~u : (u | 0x80000000u);
}
__device__ __forceinline__ float decf(unsigned u) {
    return __uint_as_float((u & 0x80000000u) ? (u ^ 0x80000000u) : ~u);
}

// ---------------------------------------------------------------------------
__global__ void k_zero(float4* __restrict__ p, int n4) {
    int i = blockIdx.x * blockDim.x + threadIdx.x;
    if (i < n4) p[i] = make_float4(0.f, 0.f, 0.f, 0.f);
}

// x[N,3] @ W1[3,32]  -> t[N,32]; also zero g_mx1
__global__ void k_xform1(const float* __restrict__ x, const float* __restrict__ W1,
                         float* __restrict__ t) {
    __shared__ float sW[96];
    int tid = threadIdx.x;
    if (tid < 96) sW[tid] = W1[tid];
    if (blockIdx.x == 0 && tid < NGR * 32) g_mx1[tid] = 0u;
    __syncthreads();
    int i = blockIdx.x * blockDim.x + tid;
    if (i >= NN) return;
    float x0 = x[i * 3 + 0], x1 = x[i * 3 + 1], x2 = x[i * 3 + 2];
    float4* to = (float4*)(t + i * 32);
#pragma unroll
    for (int c4 = 0; c4 < 8; c4++) {
        float4 r;
        r.x = fmaf(x0, sW[c4 * 4 + 0], fmaf(x1, sW[32 + c4 * 4 + 0], x2 * sW[64 + c4 * 4 + 0]));
        r.y = fmaf(x0, sW[c4 * 4 + 1], fmaf(x1, sW[32 + c4 * 4 + 1], x2 * sW[64 + c4 * 4 + 1]));
        r.z = fmaf(x0, sW[c4 * 4 + 2], fmaf(x1, sW[32 + c4 * 4 + 2], x2 * sW[64 + c4 * 4 + 2]));
        r.w = fmaf(x0, sW[c4 * 4 + 3], fmaf(x1, sW[32 + c4 * 4 + 3], x2 * sW[64 + c4 * 4 + 3]));
        to[c4] = r;
    }
}

// edge scatter: agg[dst] += t[src] * ew   (FO4 = feature_count/4, one float4/thread)
template <int FO4>
__global__ void k_scatter(const float* __restrict__ t, const float* __restrict__ ew,
                          const int* __restrict__ src, const int* __restrict__ dst,
                          float* __restrict__ agg) {
    int i = blockIdx.x * blockDim.x + threadIdx.x;
    int e = i / FO4;
    if (e >= NE) return;
    int j = i - e * FO4;
    int s = __ldg(src + e), d = __ldg(dst + e);
    float w = __ldg(ew + e);
    float4 v = *(const float4*)(t + (s * FO4 + j) * 4);
    float4 m;
    m.x = v.x * w; m.y = v.y * w; m.z = v.z * w; m.w = v.w * w;
    float* a = agg + (d * FO4 + j) * 4;
    asm volatile("red.global.add.v4.f32 [%0], {%1, %2, %3, %4};"
                 :: "l"(a), "f"(m.x), "f"(m.y), "f"(m.z), "f"(m.w)
                 : "memory");
}

// edge scatter from an 8-row pooled table: agg[dst] += tT[ids[src]] * ew
template <int FO4>
__global__ void k_scatter_pool(const float* __restrict__ tT, const float* __restrict__ ew,
                               const int* __restrict__ src, const int* __restrict__ dst,
                               const int* __restrict__ ids, float* __restrict__ agg) {
    int i = blockIdx.x * blockDim.x + threadIdx.x;
    int e = i / FO4;
    if (e >= NE) return;
    int j = i - e * FO4;
    int s = __ldg(src + e), d = __ldg(dst + e);
    float w = __ldg(ew + e);
    int g = __ldg(ids + s);
    float4 v = *(const float4*)(tT + (g * FO4 + j) * 4);
    float4 m;
    m.x = v.x * w; m.y = v.y * w; m.z = v.z * w; m.w = v.w * w;
    float* a = agg + (d * FO4 + j) * 4;
    asm volatile("red.global.add.v4.f32 [%0], {%1, %2, %3, %4};"
                 :: "l"(a), "f"(m.x), "f"(m.y), "f"(m.z), "f"(m.w)
                 : "memory");
}

// per node: h = relu(agg + bias); t = h @ W   (FI -> FO)
template <int FI, int FO>
__global__ void __launch_bounds__(128) k_relu_mm(
        const float* __restrict__ agg, const float* __restrict__ bias,
        const float* __restrict__ W, float* __restrict__ t) {
    __shared__ float sW[FI * FO];
    __shared__ float sb[FI];
    for (int k = threadIdx.x; k < FI * FO; k += blockDim.x) sW[k] = W[k];
    if (threadIdx.x < FI) sb[threadIdx.x] = bias[threadIdx.x];
    __syncthreads();
    int i = blockIdx.x * blockDim.x + threadIdx.x;
    if (i >= NN) return;

    float h[FI];
    const float4* ain = (const float4*)(agg + i * FI);
#pragma unroll
    for (int k4 = 0; k4 < FI / 4; k4++) {
        float4 a = ain[k4];
        h[k4 * 4 + 0] = fmaxf(a.x + sb[k4 * 4 + 0], 0.f);
        h[k4 * 4 + 1] = fmaxf(a.y + sb[k4 * 4 + 1], 0.f);
        h[k4 * 4 + 2] = fmaxf(a.z + sb[k4 * 4 + 2], 0.f);
        h[k4 * 4 + 3] = fmaxf(a.w + sb[k4 * 4 + 3], 0.f);
    }

    float4 acc[FO / 4];
#pragma unroll
    for (int c = 0; c < FO / 4; c++) acc[c] = make_float4(0.f, 0.f, 0.f, 0.f);
    const float4* sW4 = (const float4*)sW;
    for (int k = 0; k < FI; k++) {
        float hk = h[k];
#pragma unroll
        for (int c = 0; c < FO / 4; c++) {
            float4 wv = sW4[k * (FO / 4) + c];
            acc[c].x = fmaf(hk, wv.x, acc[c].x);
            acc[c].y = fmaf(hk, wv.y, acc[c].y);
            acc[c].z = fmaf(hk, wv.z, acc[c].z);
            acc[c].w = fmaf(hk, wv.w, acc[c].w);
        }
    }
    float4* to = (float4*)(t + i * FO);
#pragma unroll
    for (int c = 0; c < FO / 4; c++) to[c] = acc[c];
}

// per node: y = BN(relu(agg+bias)); atomicMax into per-graph table (no node output)
template <int FI>
__global__ void k_bnpool(const float* __restrict__ agg, const float* __restrict__ bias,
                         const float* __restrict__ gam, const float* __restrict__ bet,
                         const float* __restrict__ mean, const float* __restrict__ var,
                         const int* __restrict__ ids, unsigned* __restrict__ mx) {
    __shared__ float ssc[FI], ssh[FI], sb[FI];
    if (threadIdx.x < FI) {
        int k = threadIdx.x;
        float sc = gam[k] * rsqrtf(var[k] + 1e-3f);
        ssc[k] = sc;
        ssh[k] = bet[k] - mean[k] * sc;
        sb[k] = bias[k];
    }
    __syncthreads();
    int i = blockIdx.x * blockDim.x + threadIdx.x;
    if (i >= NN) return;
    int gr = __ldg(ids + i);
    unsigned* mrow = mx + gr * FI;
#pragma unroll
    for (int k = 0; k < FI; k++) {
        float hv = fmaxf(agg[i * FI + k] + sb[k], 0.f);
        float y = fmaf(hv, ssc[k], ssh[k]);
        atomicMax(mrow + k, encf(y));
    }
}

// pooled1[8,32] @ W3[32,64] -> g_tT3 ; also zero g_mx2.  1 block x 512 threads
__global__ void k_pool_mm3(const float* __restrict__ W3) {
    int tid = threadIdx.x;        // 512 == NGR*64
    g_mx2[tid] = 0u;
    int g = tid >> 6, c = tid & 63;
    float acc = 0.f;
#pragma unroll
    for (int k = 0; k < 32; k++) acc = fmaf(decf(g_mx1[g * 32 + k]), W3[k * 64 + c], acc);
    g_tT3[tid] = acc;
}

// pooled2[8,64] @ W5[64,20] -> g_tT5.  1 block x 192 threads (160 used)
__global__ void k_pool_mm5(const float* __restrict__ W5) {
    int tid = threadIdx.x;
    if (tid >= NGR * 20) return;
    int g = tid / 20, c = tid - g * 20;
    float acc = 0.f;
#pragma unroll
    for (int k = 0; k < 64; k++) acc = fmaf(decf(g_mx2[g * 64 + k]), W5[k * 20 + c], acc);
    g_tT5[tid] = acc;
}

// in-place softmax(out + b5) over 20 classes per node
__global__ void k_softmax(float* __restrict__ out, const float* __restrict__ b5) {
    __shared__ float sb[20];
    if (threadIdx.x < 20) sb[threadIdx.x] = b5[threadIdx.x];
    __syncthreads();
    int i = blockIdx.x * blockDim.x + threadIdx.x;
    if (i >= NN) return;
    float v[20];
    float mx = -3.4e38f;
#pragma unroll
    for (int c = 0; c < 20; c++) {
        v[c] = out[i * 20 + c] + sb[c];
        mx = fmaxf(mx, v[c]);
    }
    float s = 0.f;
#pragma unroll
    for (int c = 0; c < 20; c++) {
        v[c] = expf(v[c] - mx);
        s += v[c];
    }
    float inv = 1.0f / s;
#pragma unroll
    for (int c = 0; c < 20; c++) out[i * 20 + c] = v[c] * inv;
}

// ---------------------------------------------------------------------------
extern "C" void kernel_launch(void* const* d_in, const int* in_sizes, int n_in,
                              void* d_out, int out_size) {
    const float* x   = (const float*)d_in[0];
    const float* ew  = (const float*)d_in[1];
    const int*   src = (const int*)  d_in[2];
    const int*   dst = (const int*)  d_in[3];
    const int*   ids = (const int*)  d_in[4];
    const float* W1  = (const float*)d_in[5];
    const float* b1  = (const float*)d_in[6];
    const float* W2  = (const float*)d_in[7];
    const float* b2  = (const float*)d_in[8];
    const float* g1  = (const float*)d_in[9];
    const float* be1 = (const float*)d_in[10];
    const float* m1  = (const float*)d_in[11];
    const float* v1  = (const float*)d_in[12];
    const float* W3  = (const float*)d_in[13];
    const float* b3  = (const float*)d_in[14];
    const float* W4  = (const float*)d_in[15];
    const float* b4  = (const float*)d_in[16];
    const float* g2  = (const float*)d_in[17];
    const float* be2 = (const float*)d_in[18];
    const float* m2  = (const float*)d_in[19];
    const float* v2  = (const float*)d_in[20];
    const float* W5  = (const float*)d_in[21];
    const float* b5  = (const float*)d_in[22];
    float* out = (float*)d_out;

    float* bufT; float* bufA; unsigned* mx1; unsigned* mx2; float* tT3; float* tT5;
    cudaGetSymbolAddress((void**)&bufT, g_bufT);
    cudaGetSymbolAddress((void**)&bufA, g_bufA);
    cudaGetSymbolAddress((void**)&mx1,  g_mx1);
    cudaGetSymbolAddress((void**)&mx2,  g_mx2);
    cudaGetSymbolAddress((void**)&tT3,  g_tT3);
    cudaGetSymbolAddress((void**)&tT5,  g_tT5);

    const int TB = 256;
    const int nblk_node   = (NN + TB - 1) / TB;
    const int nblk_node128 = (NN + 127) / 128;
    const int n4_32 = NN * 32 / 4, n4_64 = NN * 64 / 4, n4_out = NN * 20 / 4;

    // ---- GCN1: t = xW1 ; agg = A t ; (zero mx1 inside k_xform1) ----
    k_xform1<<<nblk_node, TB>>>(x, W1, bufT);
    k_zero<<<(n4_32 + TB - 1) / TB, TB>>>((float4*)bufA, n4_32);
    k_scatter<8><<<(NE * 8 + TB - 1) / TB, TB>>>(bufT, ew, src, dst, bufA);

    // ---- relu+b1, then t2 = h1 @ W2 ----
    k_relu_mm<32, 32><<<nblk_node128, 128>>>(bufA, b1, W2, bufT);

    // ---- GCN2 aggregate ----
    k_zero<<<(n4_32 + TB - 1) / TB, TB>>>((float4*)bufA, n4_32);
    k_scatter<8><<<(NE * 8 + TB - 1) / TB, TB>>>(bufT, ew, src, dst, bufA);

    // ---- relu+b2, BN1, pool-max into mx1 ----
    k_bnpool<32><<<nblk_node, TB>>>(bufA, b2, g1, be1, m1, v1, ids, mx1);

    // ---- pooled1 @ W3 -> 8x64 table (also zeroes mx2) ----
    k_pool_mm3<<<1, NGR * 64>>>(W3);

    // ---- GCN3 aggregate (messages from 8-row table) ----
    k_zero<<<(n4_64 + TB - 1) / TB, TB>>>((float4*)bufA, n4_64);
    k_scatter_pool<16><<<(NE * 16 + TB - 1) / TB, TB>>>(tT3, ew, src, dst, ids, bufA);

    // ---- relu+b3, then t4 = h3 @ W4 ----
    k_relu_mm<64, 64><<<nblk_node128, 128>>>(bufA, b3, W4, bufT);

    // ---- GCN4 aggregate ----
    k_zero<<<(n4_64 + TB - 1) / TB, TB>>>((float4*)bufA, n4_64);
    k_scatter<16><<<(NE * 16 + TB - 1) / TB, TB>>>(bufT, ew, src, dst, bufA);

    // ---- relu+b4, BN2, pool-max into mx2 ----
    k_bnpool<64><<<nblk_node, TB>>>(bufA, b4, g2, be2, m2, v2, ids, mx2);

    // ---- pooled2 @ W5 -> 8x20 table ----
    k_pool_mm5<<<1, 192>>>(W5);

    // ---- GCN5 aggregate directly into d_out ----
    k_zero<<<(n4_out + TB - 1) / TB, TB>>>((float4*)out, n4_out);
    k_scatter_pool<5><<<(NE * 5 + TB - 1) / TB, TB>>>(tT5, ew, src, dst, ids, out);

    // ---- +b5, softmax in place ----
    k_softmax<<<nblk_node, TB>>>(out, b5);
}

// round 2
// speedup vs baseline: 8.4457x; 8.4457x over previous
#include <cuda_runtime.h>

#define NN  80000
#define NE  1280000
#define NGR 8

// ---- scratch (device globals; no runtime allocation) ----
__device__ float    g_bufT[NN * 64];     // message source (h1 / h3)
__device__ float    g_bufA[NN * 64];     // aggregation target (also aggX padded [N,4])
__device__ float    g_ws[NN * NGR];      // per-dst, per-src-graph edge-weight sums
__device__ unsigned g_mx1[NGR * 32];     // encoded per-graph max, stage 1
__device__ unsigned g_mx2[NGR * 64];     // encoded per-graph max, stage 2
__device__ float    g_tT3[NGR * 64];     // pooled1 @ W3
__device__ float    g_tT5[NGR * 20];     // pooled2 @ W5

// ordered-uint encoding of float for atomicMax (monotonic; 0u below all finite)
__device__ __forceinline__ unsigned encf(float f) {
    unsigned u = __float_as_uint(f);
    return (u & 0x80000000u) ? ~u : (u | 0x80000000u);
}
__device__ __forceinline__ float decf(unsigned u) {
    return __uint_as_float((u & 0x80000000u) ? (u ^ 0x80000000u) : ~u);
}

// ---------------------------------------------------------------------------
__global__ void k_zero(float4* __restrict__ p, int n4) {
    int i = blockIdx.x * blockDim.x + threadIdx.x;
    if (i < n4) p[i] = make_float4(0.f, 0.f, 0.f, 0.f);
}

// zero three regions (aggX, ws, both mx tables)
__global__ void k_zero3(float4* __restrict__ a, int na,
                        float4* __restrict__ b, int nb,
                        float4* __restrict__ c, int nc) {
    int i = blockIdx.x * blockDim.x + threadIdx.x;
    float4 z = make_float4(0.f, 0.f, 0.f, 0.f);
    if (i < na) a[i] = z;
    if (i < nb) b[i] = z;
    if (i < nc) c[i] = z;
}

// edge pass 1: aggX[dst] += x[src]*w (padded stride 4), ws[dst][ids[src]] += w
__global__ void k_pass1(const float* __restrict__ x, const float* __restrict__ ew,
                        const int* __restrict__ src, const int* __restrict__ dst,
                        const int* __restrict__ ids,
                        float* __restrict__ aggX, float* __restrict__ ws) {
    int e = blockIdx.x * blockDim.x + threadIdx.x;
    if (e >= NE) return;
    int s = __ldg(src + e), d = __ldg(dst + e);
    float w = __ldg(ew + e);
    float x0 = __ldg(x + s * 3 + 0), x1 = __ldg(x + s * 3 + 1), x2 = __ldg(x + s * 3 + 2);
    int g = __ldg(ids + s);
    float* a = aggX + d * 4;
    asm volatile("red.global.add.v4.f32 [%0], {%1, %2, %3, %4};"
                 :: "l"(a), "f"(x0 * w), "f"(x1 * w), "f"(x2 * w), "f"(0.f)
                 : "memory");
    atomicAdd(ws + d * NGR + g, w);
}

// h1 = relu(aggX @ W1 + b1)  [N,32]
__global__ void k_h1(const float* __restrict__ aggX, const float* __restrict__ W1,
                     const float* __restrict__ b1, float* __restrict__ h1) {
    __shared__ float sW[96], sb[32];
    int tid = threadIdx.x;
    if (tid < 96) sW[tid] = W1[tid];
    if (tid < 32) sb[tid] = b1[tid];
    __syncthreads();
    int i = blockIdx.x * blockDim.x + tid;
    if (i >= NN) return;
    float4 a = ((const float4*)aggX)[i];
    float4* to = (float4*)(h1 + i * 32);
#pragma unroll
    for (int c4 = 0; c4 < 8; c4++) {
        float4 r;
#pragma unroll
        for (int u = 0; u < 4; u++) {
            int c = c4 * 4 + u;
            float v = fmaf(a.x, sW[c], fmaf(a.y, sW[32 + c], fmaf(a.z, sW[64 + c], sb[c])));
            ((float*)&r)[u] = fmaxf(v, 0.f);
        }
        to[c4] = r;
    }
}

// edge scatter: agg[dst] += t[src] * ew   (FO4 float4s per edge, one per thread)
template <int FO4>
__global__ void k_scatter(const float* __restrict__ t, const float* __restrict__ ew,
                          const int* __restrict__ src, const int* __restrict__ dst,
                          float* __restrict__ agg) {
    int i = blockIdx.x * blockDim.x + threadIdx.x;
    int e = i / FO4;
    if (e >= NE) return;
    int j = i - e * FO4;
    int s = __ldg(src + e), d = __ldg(dst + e);
    float w = __ldg(ew + e);
    float4 v = *(const float4*)(t + (s * FO4 + j) * 4);
    float* a = agg + (d * FO4 + j) * 4;
    asm volatile("red.global.add.v4.f32 [%0], {%1, %2, %3, %4};"
                 :: "l"(a), "f"(v.x * w), "f"(v.y * w), "f"(v.z * w), "f"(v.w * w)
                 : "memory");
}

// per node: acc = aggH @ W (FIxFI); y = BN(relu(acc + b)); per-graph max-pool.
// TPN = FI/16 threads per node, each owning 16 output columns.
template <int FI>
__global__ void __launch_bounds__(256) k_mm_bn_pool(
        const float* __restrict__ agg, const float* __restrict__ bias,
        const float* __restrict__ W,
        const float* __restrict__ gam, const float* __restrict__ bet,
        const float* __restrict__ mean, const float* __restrict__ var,
        const int* __restrict__ ids, unsigned* __restrict__ mx) {
    constexpr int TPN = FI / 16;
    constexpr int NPB = 256 / TPN;
    __shared__ float sW[FI * FI];
    __shared__ float ssc[FI], ssh[FI], sbv[FI];
    __shared__ unsigned stab[NGR * FI];
    int tid = threadIdx.x;
    for (int k = tid; k < FI * FI; k += 256) sW[k] = W[k];
    if (tid < FI) {
        float sc = gam[tid] * rsqrtf(var[tid] + 1e-3f);
        ssc[tid] = sc;
        ssh[tid] = bet[tid] - mean[tid] * sc;
        sbv[tid] = bias[tid];
    }
    for (int k = tid; k < NGR * FI; k += 256) stab[k] = 0u;
    __syncthreads();

    int i = blockIdx.x * NPB + tid / TPN;
    int coff = (tid % TPN) * 16;
    if (i < NN) {
        const float4* arow = (const float4*)(agg + (size_t)i * FI);
        float acc[16];
#pragma unroll
        for (int c = 0; c < 16; c++) acc[c] = 0.f;
#pragma unroll
        for (int k4 = 0; k4 < FI / 4; k4++) {
            float4 a = arow[k4];
            const float* wr = sW + (k4 * 4) * FI + coff;
#pragma unroll
            for (int c = 0; c < 16; c++) acc[c] = fmaf(a.x, wr[c], acc[c]);
            wr += FI;
#pragma unroll
            for (int c = 0; c < 16; c++) acc[c] = fmaf(a.y, wr[c], acc[c]);
            wr += FI;
#pragma unroll
            for (int c = 0; c < 16; c++) acc[c] = fmaf(a.z, wr[c], acc[c]);
            wr += FI;
#pragma unroll
            for (int c = 0; c < 16; c++) acc[c] = fmaf(a.w, wr[c], acc[c]);
        }
        int g = __ldg(ids + i);
        unsigned* srow = stab + g * FI + coff;
#pragma unroll
        for (int c = 0; c < 16; c++) {
            float hv = fmaxf(acc[c] + sbv[coff + c], 0.f);
            float y = fmaf(hv, ssc[coff + c], ssh[coff + c]);
            atomicMax(srow + c, encf(y));
        }
    }
    __syncthreads();
    for (int k = tid; k < NGR * FI; k += 256) {
        unsigned v = stab[k];
        if (v) atomicMax(mx + k, v);
    }
}

// pooled1[8,32] @ W3[32,64] -> g_tT3.  1 block x 512 threads
__global__ void k_pool_mm3(const float* __restrict__ W3) {
    int tid = threadIdx.x;
    int g = tid >> 6, c = tid & 63;
    float acc = 0.f;
#pragma unroll
    for (int k = 0; k < 32; k++) acc = fmaf(decf(g_mx1[g * 32 + k]), W3[k * 64 + c], acc);
    g_tT3[tid] = acc;
}

// pooled2[8,64] @ W5[64,20] -> g_tT5.  1 block x 192 threads (160 used)
__global__ void k_pool_mm5(const float* __restrict__ W5) {
    int tid = threadIdx.x;
    if (tid >= NGR * 20) return;
    int g = tid / 20, c = tid - g * 20;
    float acc = 0.f;
#pragma unroll
    for (int k = 0; k < 64; k++) acc = fmaf(decf(g_mx2[g * 64 + k]), W5[k * 20 + c], acc);
    g_tT5[tid] = acc;
}

// h3 = relu(ws @ tT3 + b3)  [N,64]; 4 threads per node x 16 cols
__global__ void __launch_bounds__(256) k_h3(const float* __restrict__ ws,
                                            const float* __restrict__ b3,
                                            float* __restrict__ h3) {
    __shared__ float sT[NGR * 64], sb[64];
    int tid = threadIdx.x;
    for (int k = tid; k < NGR * 64; k += 256) sT[k] = g_tT3[k];
    if (tid < 64) sb[tid] = b3[tid];
    __syncthreads();
    int i = blockIdx.x * 64 + tid / 4;
    int coff = (tid % 4) * 16;
    if (i >= NN) return;
    const float4* wsr = (const float4*)(ws + i * NGR);
    float4 w0 = wsr[0], w1 = wsr[1];
    float wg[8] = {w0.x, w0.y, w0.z, w0.w, w1.x, w1.y, w1.z, w1.w};
    float acc[16];
#pragma unroll
    for (int c = 0; c < 16; c++) acc[c] = 0.f;
#pragma unroll
    for (int g = 0; g < 8; g++) {
        const float* tr = sT + g * 64 + coff;
#pragma unroll
        for (int c = 0; c < 16; c++) acc[c] = fmaf(wg[g], tr[c], acc[c]);
    }
    float4* to = (float4*)(h3 + (size_t)i * 64 + coff);
#pragma unroll
    for (int c4 = 0; c4 < 4; c4++) {
        float4 r;
#pragma unroll
        for (int u = 0; u < 4; u++)
            ((float*)&r)[u] = fmaxf(acc[c4 * 4 + u] + sb[coff + c4 * 4 + u], 0.f);
        to[c4] = r;
    }
}

// out = softmax(ws @ tT5 + b5)  [N,20]
__global__ void k_out(const float* __restrict__ ws, const float* __restrict__ b5,
                      float* __restrict__ out) {
    __shared__ float sT[NGR * 20], sb[20];
    int tid = threadIdx.x;
    for (int k = tid; k < NGR * 20; k += 256) sT[k] = g_tT5[k];
    if (tid < 20) sb[tid] = b5[tid];
    __syncthreads();
    int i = blockIdx.x * blockDim.x + tid;
    if (i >= NN) return;
    const float4* wsr = (const float4*)(ws + i * NGR);
    float4 w0 = wsr[0], w1 = wsr[1];
    float wg[8] = {w0.x, w0.y, w0.z, w0.w, w1.x, w1.y, w1.z, w1.w};
    float o[20];
#pragma unroll
    for (int c = 0; c < 20; c++) o[c] = sb[c];
#pragma unroll
    for (int g = 0; g < 8; g++) {
        const float* tr = sT + g * 20;
#pragma unroll
        for (int c = 0; c < 20; c++) o[c] = fmaf(wg[g], tr[c], o[c]);
    }
    float mx = -3.4e38f;
#pragma unroll
    for (int c = 0; c < 20; c++) mx = fmaxf(mx, o[c]);
    float s = 0.f;
#pragma unroll
    for (int c = 0; c < 20; c++) { o[c] = __expf(o[c] - mx); s += o[c]; }
    float inv = 1.0f / s;
    float4* to = (float4*)(out + (size_t)i * 20);
#pragma unroll
    for (int c4 = 0; c4 < 5; c4++) {
        float4 r;
#pragma unroll
        for (int u = 0; u < 4; u++) ((float*)&r)[u] = o[c4 * 4 + u] * inv;
        to[c4] = r;
    }
}

// ---------------------------------------------------------------------------
extern "C" void kernel_launch(void* const* d_in, const int* in_sizes, int n_in,
                              void* d_out, int out_size) {
    const float* x   = (const float*)d_in[0];
    const float* ew  = (const float*)d_in[1];
    const int*   src = (const int*)  d_in[2];
    const int*   dst = (const int*)  d_in[3];
    const int*   ids = (const int*)  d_in[4];
    const float* W1  = (const float*)d_in[5];
    const float* b1  = (const float*)d_in[6];
    const float* W2  = (const float*)d_in[7];
    const float* b2  = (const float*)d_in[8];
    const float* g1  = (const float*)d_in[9];
    const float* be1 = (const float*)d_in[10];
    const float* m1  = (const float*)d_in[11];
    const float* v1  = (const float*)d_in[12];
    const float* W3  = (const float*)d_in[13];
    const float* b3  = (const float*)d_in[14];
    const float* W4  = (const float*)d_in[15];
    const float* b4  = (const float*)d_in[16];
    const float* g2  = (const float*)d_in[17];
    const float* be2 = (const float*)d_in[18];
    const float* m2  = (const float*)d_in[19];
    const float* v2  = (const float*)d_in[20];
    const float* W5  = (const float*)d_in[21];
    const float* b5  = (const float*)d_in[22];
    float* out = (float*)d_out;

    float* bufT; float* bufA; float* ws; unsigned* mx1; unsigned* mx2;
    cudaGetSymbolAddress((void**)&bufT, g_bufT);
    cudaGetSymbolAddress((void**)&bufA, g_bufA);
    cudaGetSymbolAddress((void**)&ws,   g_ws);
    cudaGetSymbolAddress((void**)&mx1,  g_mx1);
    cudaGetSymbolAddress((void**)&mx2,  g_mx2);

    const int TB = 256;
    const int nblk_node = (NN + TB - 1) / TB;

    // zero aggX [N,4], ws [N,8], mx1+mx2 (contiguous? no — zero mx1 via 3rd slot, mx2 appended by pointer math not safe; use two slots)
    k_zero3<<<(NN * 2 + TB - 1) / TB, TB>>>(
        (float4*)bufA, NN,              // aggX: N float4
        (float4*)ws,   NN * 2,          // ws:   N*8 floats
        (float4*)mx1,  NGR * 32 / 4);   // mx1
    k_zero<<<1, 128>>>((float4*)mx2, NGR * 64 / 4);

    // edge pass 1: aggX += x[src]*w (stride4), ws histogram
    k_pass1<<<(NE + TB - 1) / TB, TB>>>(x, ew, src, dst, ids, bufA, ws);

    // h1 = relu(aggX @ W1 + b1) -> bufT [N,32]
    k_h1<<<nblk_node, TB>>>(bufA, W1, b1, bufT);

    // GCN2 aggregate: aggH1 = A h1
    k_zero<<<(NN * 32 / 4 + TB - 1) / TB, TB>>>((float4*)bufA, NN * 32 / 4);
    k_scatter<8><<<(NE * 8 + TB - 1) / TB, TB>>>(bufT, ew, src, dst, bufA);

    // agg2 = aggH1 @ W2; BN1(relu(+b2)); pool -> mx1
    k_mm_bn_pool<32><<<(NN + 127) / 128, 256>>>(bufA, b2, W2, g1, be1, m1, v1, ids, mx1);

    // tT3 = pooled1 @ W3
    k_pool_mm3<<<1, NGR * 64>>>(W3);

    // h3 = relu(ws @ tT3 + b3) -> bufT [N,64]
    k_h3<<<(NN + 63) / 64, 256>>>(ws, b3, bufT);

    // GCN4 aggregate: aggH3 = A h3
    k_zero<<<(NN * 64 / 4 + TB - 1) / TB, TB>>>((float4*)bufA, NN * 64 / 4);
    k_scatter<16><<<(NE * 16 + TB - 1) / TB, TB>>>(bufT, ew, src, dst, bufA);

    // agg4 = aggH3 @ W4; BN2(relu(+b4)); pool -> mx2
    k_mm_bn_pool<64><<<(NN + 63) / 64, 256>>>(bufA, b4, W4, g2, be2, m2, v2, ids, mx2);

    // tT5 = pooled2 @ W5
    k_pool_mm5<<<1, 192>>>(W5);

    // out = softmax(ws @ tT5 + b5)
    k_out<<<nblk_node, TB>>>(ws, b5, out);
}

// round 3
// speedup vs baseline: 9.0607x; 1.0728x over previous
#include <cuda_runtime.h>

#define NN  80000
#define NE  1280000
#define NGR 8
#define CAP 96

// ---- scratch (device globals; no runtime allocation) ----
__device__ float    g_bufT[NN * 64];       // message source (h1 / h3)
__device__ float    g_bufA[NN * 64];       // aggregation result
__device__ float    g_aggX[NN * 4];        // aggregated x (padded)
__device__ float    g_ws[NN * NGR];        // per-dst, per-src-graph edge-weight sums
__device__ int      g_cnt[NN];             // per-dst degree counter
__device__ int2     g_bkt[(size_t)NN * CAP]; // per-dst (src, w) buckets
__device__ unsigned g_mx1[NGR * 32];
__device__ unsigned g_mx2[NGR * 64];
__device__ float    g_tT3[NGR * 64];
__device__ float    g_tT5[NGR * 20];

__device__ __forceinline__ unsigned encf(float f) {
    unsigned u = __float_as_uint(f);
    return (u & 0x80000000u) ? ~u : (u | 0x80000000u);
}
__device__ __forceinline__ float decf(unsigned u) {
    return __uint_as_float((u & 0x80000000u) ? (u ^ 0x80000000u) : ~u);
}

// ---------------------------------------------------------------------------
// zero degree counters + pool-max tables
__global__ void k_init() {
    int i = blockIdx.x * blockDim.x + threadIdx.x;
    if (i < NN) g_cnt[i] = 0;
    if (i < NGR * 32) g_mx1[i] = 0u;
    if (i < NGR * 64) g_mx2[i] = 0u;
}

// edge-parallel bucket fill: bucket[dst] <- (src, w)
__global__ void k_fill(const int* __restrict__ src, const int* __restrict__ dst,
                       const float* __restrict__ ew) {
    int e = blockIdx.x * blockDim.x + threadIdx.x;
    if (e >= NE) return;
    int d = __ldg(dst + e);
    int k = atomicAdd(g_cnt + d, 1);
    if (k < CAP)
        g_bkt[(size_t)d * CAP + k] = make_int2(__ldg(src + e), __float_as_int(__ldg(ew + e)));
}

// pass1: per-dst gather of x (3-dim) and ws histogram (8 graphs). thread per dst.
__global__ void k_pass1g(const float* __restrict__ x, const int* __restrict__ ids) {
    int d = blockIdx.x * blockDim.x + threadIdx.x;
    if (d >= NN) return;
    int cnt = min(g_cnt[d], CAP);
    const int2* bk = g_bkt + (size_t)d * CAP;
    float a0 = 0.f, a1 = 0.f, a2 = 0.f;
    float h[8];
#pragma unroll
    for (int g = 0; g < 8; g++) h[g] = 0.f;
    for (int k = 0; k < cnt; k++) {
        int2 m = __ldg(bk + k);
        int s = m.x;
        float w = __int_as_float(m.y);
        a0 = fmaf(w, __ldg(x + s * 3 + 0), a0);
        a1 = fmaf(w, __ldg(x + s * 3 + 1), a1);
        a2 = fmaf(w, __ldg(x + s * 3 + 2), a2);
        int g = __ldg(ids + s);
#pragma unroll
        for (int gg = 0; gg < 8; gg++) h[gg] += (gg == g) ? w : 0.f;
    }
    ((float4*)g_aggX)[d] = make_float4(a0, a1, a2, 0.f);
    float4* wsr = (float4*)(g_ws + d * NGR);
    wsr[0] = make_float4(h[0], h[1], h[2], h[3]);
    wsr[1] = make_float4(h[4], h[5], h[6], h[7]);
}

// h1 = relu(aggX @ W1 + b1)  [N,32]
__global__ void k_h1(const float* __restrict__ W1, const float* __restrict__ b1,
                     float* __restrict__ h1) {
    __shared__ float sW[96], sb[32];
    int tid = threadIdx.x;
    if (tid < 96) sW[tid] = W1[tid];
    if (tid < 32) sb[tid] = b1[tid];
    __syncthreads();
    int i = blockIdx.x * blockDim.x + tid;
    if (i >= NN) return;
    float4 a = ((const float4*)g_aggX)[i];
    float4* to = (float4*)(h1 + i * 32);
#pragma unroll
    for (int c4 = 0; c4 < 8; c4++) {
        float4 r;
#pragma unroll
        for (int u = 0; u < 4; u++) {
            int c = c4 * 4 + u;
            float v = fmaf(a.x, sW[c], fmaf(a.y, sW[32 + c], fmaf(a.z, sW[64 + c], sb[c])));
            ((float*)&r)[u] = fmaxf(v, 0.f);
        }
        to[c4] = r;
    }
}

// warp-per-dst gather reduction, 32 features (1 float/lane), 4-edge unroll
__global__ void __launch_bounds__(256) k_gather32(const float* __restrict__ t,
                                                  float* __restrict__ agg) {
    int wid = (blockIdx.x * 256 + threadIdx.x) >> 5;
    int lane = threadIdx.x & 31;
    if (wid >= NN) return;
    int cnt = min(g_cnt[wid], CAP);
    const int2* bk = g_bkt + (size_t)wid * CAP;
    float acc = 0.f;
    int k = 0;
    for (; k + 4 <= cnt; k += 4) {
        int4 a = *(const int4*)(bk + k);
        int4 b = *(const int4*)(bk + k + 2);
        float v0 = __ldg(t + (size_t)a.x * 32 + lane);
        float v1 = __ldg(t + (size_t)a.z * 32 + lane);
        float v2 = __ldg(t + (size_t)b.x * 32 + lane);
        float v3 = __ldg(t + (size_t)b.z * 32 + lane);
        acc = fmaf(__int_as_float(a.y), v0, acc);
        acc = fmaf(__int_as_float(a.w), v1, acc);
        acc = fmaf(__int_as_float(b.y), v2, acc);
        acc = fmaf(__int_as_float(b.w), v3, acc);
    }
    for (; k < cnt; k++) {
        int2 m = bk[k];
        acc = fmaf(__int_as_float(m.y), __ldg(t + (size_t)m.x * 32 + lane), acc);
    }
    agg[(size_t)wid * 32 + lane] = acc;
}

// warp-per-dst gather reduction, 64 features (float2/lane), 4-edge unroll
__global__ void __launch_bounds__(256) k_gather64(const float* __restrict__ t,
                                                  float* __restrict__ agg) {
    int wid = (blockIdx.x * 256 + threadIdx.x) >> 5;
    int lane = threadIdx.x & 31;
    if (wid >= NN) return;
    int cnt = min(g_cnt[wid], CAP);
    const int2* bk = g_bkt + (size_t)wid * CAP;
    const float2* tp = (const float2*)t;   // row stride = 32 float2
    float2 acc = make_float2(0.f, 0.f);
    int k = 0;
    for (; k + 4 <= cnt; k += 4) {
        int4 a = *(const int4*)(bk + k);
        int4 b = *(const int4*)(bk + k + 2);
        float2 v0 = __ldg(tp + (size_t)a.x * 32 + lane);
        float2 v1 = __ldg(tp + (size_t)a.z * 32 + lane);
        float2 v2 = __ldg(tp + (size_t)b.x * 32 + lane);
        float2 v3 = __ldg(tp + (size_t)b.z * 32 + lane);
        float w0 = __int_as_float(a.y), w1 = __int_as_float(a.w);
        float w2 = __int_as_float(b.y), w3 = __int_as_float(b.w);
        acc.x = fmaf(w0, v0.x, acc.x); acc.y = fmaf(w0, v0.y, acc.y);
        acc.x = fmaf(w1, v1.x, acc.x); acc.y = fmaf(w1, v1.y, acc.y);
        acc.x = fmaf(w2, v2.x, acc.x); acc.y = fmaf(w2, v2.y, acc.y);
        acc.x = fmaf(w3, v3.x, acc.x); acc.y = fmaf(w3, v3.y, acc.y);
    }
    for (; k < cnt; k++) {
        int2 m = bk[k];
        float2 v = __ldg(tp + (size_t)m.x * 32 + lane);
        float w = __int_as_float(m.y);
        acc.x = fmaf(w, v.x, acc.x); acc.y = fmaf(w, v.y, acc.y);
    }
    ((float2*)agg)[(size_t)wid * 32 + lane] = acc;
}

// per node: acc = aggH @ W (FIxFI); y = BN(relu(acc + b)); per-graph max-pool.
template <int FI>
__global__ void __launch_bounds__(256) k_mm_bn_pool(
        const float* __restrict__ agg, const float* __restrict__ bias,
        const float* __restrict__ W,
        const float* __restrict__ gam, const float* __restrict__ bet,
        const float* __restrict__ mean, const float* __restrict__ var,
        const int* __restrict__ ids, unsigned* __restrict__ mx) {
    constexpr int TPN = FI / 16;
    constexpr int NPB = 256 / TPN;
    __shared__ float sW[FI * FI];
    __shared__ float ssc[FI], ssh[FI], sbv[FI];
    __shared__ unsigned stab[NGR * FI];
    int tid = threadIdx.x;
    for (int k = tid; k < FI * FI; k += 256) sW[k] = W[k];
    if (tid < FI) {
        float sc = gam[tid] * rsqrtf(var[tid] + 1e-3f);
        ssc[tid] = sc;
        ssh[tid] = bet[tid] - mean[tid] * sc;
        sbv[tid] = bias[tid];
    }
    for (int k = tid; k < NGR * FI; k += 256) stab[k] = 0u;
    __syncthreads();

    int i = blockIdx.x * NPB + tid / TPN;
    int coff = (tid % TPN) * 16;
    if (i < NN) {
        const float4* arow = (const float4*)(agg + (size_t)i * FI);
        float acc[16];
#pragma unroll
        for (int c = 0; c < 16; c++) acc[c] = 0.f;
#pragma unroll
        for (int k4 = 0; k4 < FI / 4; k4++) {
            float4 a = arow[k4];
            const float* wr = sW + (k4 * 4) * FI + coff;
#pragma unroll
            for (int c = 0; c < 16; c++) acc[c] = fmaf(a.x, wr[c], acc[c]);
            wr += FI;
#pragma unroll
            for (int c = 0; c < 16; c++) acc[c] = fmaf(a.y, wr[c], acc[c]);
            wr += FI;
#pragma unroll
            for (int c = 0; c < 16; c++) acc[c] = fmaf(a.z, wr[c], acc[c]);
            wr += FI;
#pragma unroll
            for (int c = 0; c < 16; c++) acc[c] = fmaf(a.w, wr[c], acc[c]);
        }
        int g = __ldg(ids + i);
        unsigned* srow = stab + g * FI + coff;
#pragma unroll
        for (int c = 0; c < 16; c++) {
            float hv = fmaxf(acc[c] + sbv[coff + c], 0.f);
            float y = fmaf(hv, ssc[coff + c], ssh[coff + c]);
            atomicMax(srow + c, encf(y));
        }
    }
    __syncthreads();
    for (int k = tid; k < NGR * FI; k += 256) {
        unsigned v = stab[k];
        if (v) atomicMax(mx + k, v);
    }
}

// pooled1[8,32] @ W3[32,64] -> g_tT3.  1 block x 512 threads
__global__ void k_pool_mm3(const float* __restrict__ W3) {
    int tid = threadIdx.x;
    int g = tid >> 6, c = tid & 63;
    float acc = 0.f;
#pragma unroll
    for (int k = 0; k < 32; k++) acc = fmaf(decf(g_mx1[g * 32 + k]), W3[k * 64 + c], acc);
    g_tT3[tid] = acc;
}

// pooled2[8,64] @ W5[64,20] -> g_tT5.
__global__ void k_pool_mm5(const float* __restrict__ W5) {
    int tid = threadIdx.x;
    if (tid >= NGR * 20) return;
    int g = tid / 20, c = tid - g * 20;
    float acc = 0.f;
#pragma unroll
    for (int k = 0; k < 64; k++) acc = fmaf(decf(g_mx2[g * 64 + k]), W5[k * 20 + c], acc);
    g_tT5[tid] = acc;
}

// h3 = relu(ws @ tT3 + b3)  [N,64]; 4 threads per node x 16 cols
__global__ void __launch_bounds__(256) k_h3(const float* __restrict__ ws,
                                            const float* __restrict__ b3,
                                            float* __restrict__ h3) {
    __shared__ float sT[NGR * 64], sb[64];
    int tid = threadIdx.x;
    for (int k = tid; k < NGR * 64; k += 256) sT[k] = g_tT3[k];
    if (tid < 64) sb[tid] = b3[tid];
    __syncthreads();
    int i = blockIdx.x * 64 + tid / 4;
    int coff = (tid % 4) * 16;
    if (i >= NN) return;
    const float4* wsr = (const float4*)(ws + i * NGR);
    float4 w0 = wsr[0], w1 = wsr[1];
    float wg[8] = {w0.x, w0.y, w0.z, w0.w, w1.x, w1.y, w1.z, w1.w};
    float acc[16];
#pragma unroll
    for (int c = 0; c < 16; c++) acc[c] = 0.f;
#pragma unroll
    for (int g = 0; g < 8; g++) {
        const float* tr = sT + g * 64 + coff;
#pragma unroll
        for (int c = 0; c < 16; c++) acc[c] = fmaf(wg[g], tr[c], acc[c]);
    }
    float4* to = (float4*)(h3 + (size_t)i * 64 + coff);
#pragma unroll
    for (int c4 = 0; c4 < 4; c4++) {
        float4 r;
#pragma unroll
        for (int u = 0; u < 4; u++)
            ((float*)&r)[u] = fmaxf(acc[c4 * 4 + u] + sb[coff + c4 * 4 + u], 0.f);
        to[c4] = r;
    }
}

// out = softmax(ws @ tT5 + b5)  [N,20]
__global__ void k_out(const float* __restrict__ ws, const float* __restrict__ b5,
                      float* __restrict__ out) {
    __shared__ float sT[NGR * 20], sb[20];
    int tid = threadIdx.x;
    for (int k = tid; k < NGR * 20; k += 256) sT[k] = g_tT5[k];
    if (tid < 20) sb[tid] = b5[tid];
    __syncthreads();
    int i = blockIdx.x * blockDim.x + tid;
    if (i >= NN) return;
    const float4* wsr = (const float4*)(ws + i * NGR);
    float4 w0 = wsr[0], w1 = wsr[1];
    float wg[8] = {w0.x, w0.y, w0.z, w0.w, w1.x, w1.y, w1.z, w1.w};
    float o[20];
#pragma unroll
    for (int c = 0; c < 20; c++) o[c] = sb[c];
#pragma unroll
    for (int g = 0; g < 8; g++) {
        const float* tr = sT + g * 20;
#pragma unroll
        for (int c = 0; c < 20; c++) o[c] = fmaf(wg[g], tr[c], o[c]);
    }
    float mx = -3.4e38f;
#pragma unroll
    for (int c = 0; c < 20; c++) mx = fmaxf(mx, o[c]);
    float s = 0.f;
#pragma unroll
    for (int c = 0; c < 20; c++) { o[c] = __expf(o[c] - mx); s += o[c]; }
    float inv = 1.0f / s;
    float4* to = (float4*)(out + (size_t)i * 20);
#pragma unroll
    for (int c4 = 0; c4 < 5; c4++) {
        float4 r;
#pragma unroll
        for (int u = 0; u < 4; u++) ((float*)&r)[u] = o[c4 * 4 + u] * inv;
        to[c4] = r;
    }
}

// ---------------------------------------------------------------------------
extern "C" void kernel_launch(void* const* d_in, const int* in_sizes, int n_in,
                              void* d_out, int out_size) {
    const float* x   = (const float*)d_in[0];
    const float* ew  = (const float*)d_in[1];
    const int*   src = (const int*)  d_in[2];
    const int*   dst = (const int*)  d_in[3];
    const int*   ids = (const int*)  d_in[4];
    const float* W1  = (const float*)d_in[5];
    const float* b1  = (const float*)d_in[6];
    const float* W2  = (const float*)d_in[7];
    const float* b2  = (const float*)d_in[8];
    const float* g1  = (const float*)d_in[9];
    const float* be1 = (const float*)d_in[10];
    const float* m1  = (const float*)d_in[11];
    const float* v1  = (const float*)d_in[12];
    const float* W3  = (const float*)d_in[13];
    const float* b3  = (const float*)d_in[14];
    const float* W4  = (const float*)d_in[15];
    const float* b4  = (const float*)d_in[16];
    const float* g2  = (const float*)d_in[17];
    const float* be2 = (const float*)d_in[18];
    const float* m2  = (const float*)d_in[19];
    const float* v2  = (const float*)d_in[20];
    const float* W5  = (const float*)d_in[21];
    const float* b5  = (const float*)d_in[22];
    float* out = (float*)d_out;

    float* bufT; float* bufA; float* ws; unsigned* mx1; unsigned* mx2;
    cudaGetSymbolAddress((void**)&bufT, g_bufT);
    cudaGetSymbolAddress((void**)&bufA, g_bufA);
    cudaGetSymbolAddress((void**)&ws,   g_ws);
    cudaGetSymbolAddress((void**)&mx1,  g_mx1);
    cudaGetSymbolAddress((void**)&mx2,  g_mx2);

    const int TB = 256;
    const int nblk_node = (NN + TB - 1) / TB;
    const int nblk_edge = (NE + TB - 1) / TB;
    const int nblk_warp = (NN * 32 + TB - 1) / TB;   // warp-per-dst kernels

    // build per-dst buckets
    k_init<<<nblk_node, TB>>>();
    k_fill<<<nblk_edge, TB>>>(src, dst, ew);

    // pass1: aggX (x-agg) + ws histogram, gather-side
    k_pass1g<<<nblk_node, TB>>>(x, ids);

    // h1 = relu(aggX @ W1 + b1) -> bufT [N,32]
    k_h1<<<nblk_node, TB>>>(W1, b1, bufT);

    // GCN2 aggregate via gather
    k_gather32<<<nblk_warp, TB>>>(bufT, bufA);

    // agg2 @ W2; BN1(relu(+b2)); pool -> mx1
    k_mm_bn_pool<32><<<(NN + 127) / 128, 256>>>(bufA, b2, W2, g1, be1, m1, v1, ids, mx1);

    // tT3 = pooled1 @ W3
    k_pool_mm3<<<1, NGR * 64>>>(W3);

    // h3 = relu(ws @ tT3 + b3) -> bufT [N,64]
    k_h3<<<(NN + 63) / 64, 256>>>(ws, b3, bufT);

    // GCN4 aggregate via gather
    k_gather64<<<nblk_warp, TB>>>(bufT, bufA);

    // agg4 @ W4; BN2(relu(+b4)); pool -> mx2
    k_mm_bn_pool<64><<<(NN + 63) / 64, 256>>>(bufA, b4, W4, g2, be2, m2, v2, ids, mx2);

    // tT5 = pooled2 @ W5
    k_pool_mm5<<<1, 192>>>(W5);

    // out = softmax(ws @ tT5 + b5)
    k_out<<<nblk_node, TB>>>(ws, b5, out);
}

// round 4
// speedup vs baseline: 9.0985x; 1.0042x over previous
#include <cuda_runtime.h>

#define NN  80000
#define NE  1280000
#define NGR 8
#define CAP 64
#define SMASK 0xFFFFF

// ---- scratch (device globals; no runtime allocation) ----
__device__ float    g_h3[NN * 64];          // h3 message table
__device__ float    g_agg[NN * 64];         // aggregation result (32 or 64 wide)
__device__ float    g_aggX[NN * 4];         // aggregated x (padded to 4)
__device__ float    g_ws[NN * NGR];         // per-dst per-src-graph edge-weight sums
__device__ int      g_cnt[NN];              // per-dst degree
__device__ int2     g_bkt[(size_t)NN * CAP]; // per-dst (src|g<<20, w)
__device__ unsigned g_mx1[NGR * 32];
__device__ unsigned g_mx2[NGR * 64];

__device__ __forceinline__ unsigned encf(float f) {
    unsigned u = __float_as_uint(f);
    return (u & 0x80000000u) ? ~u : (u | 0x80000000u);
}
__device__ __forceinline__ float decf(unsigned u) {
    return __uint_as_float((u & 0x80000000u) ? (u ^ 0x80000000u) : ~u);
}

// ---------------------------------------------------------------------------
// zero: cnt, aggX, pool tables
__global__ void k_init() {
    int i = blockIdx.x * blockDim.x + threadIdx.x;
    if (i < NN) {
        g_cnt[i] = 0;
        ((float4*)g_aggX)[i] = make_float4(0.f, 0.f, 0.f, 0.f);
    }
    if (i < NGR * 32) g_mx1[i] = 0u;
    if (i < NGR * 64) g_mx2[i] = 0u;
}

// edge-parallel: bucket fill (src|g<<20, w) + aggX[dst] += x[src]*w
__global__ void k_fill(const int* __restrict__ src, const int* __restrict__ dst,
                       const float* __restrict__ ew, const int* __restrict__ ids,
                       const float* __restrict__ x) {
    int e = blockIdx.x * blockDim.x + threadIdx.x;
    if (e >= NE) return;
    int s = __ldg(src + e), d = __ldg(dst + e);
    float w = __ldg(ew + e);
    int g = __ldg(ids + s);
    int k = atomicAdd(g_cnt + d, 1);
    if (k < CAP)
        g_bkt[(size_t)d * CAP + k] = make_int2(s | (g << 20), __float_as_int(w));
    float x0 = __ldg(x + s * 3 + 0), x1 = __ldg(x + s * 3 + 1), x2 = __ldg(x + s * 3 + 2);
    float* a = g_aggX + d * 4;
    asm volatile("red.global.add.v4.f32 [%0], {%1, %2, %3, %4};"
                 :: "l"(a), "f"(x0 * w), "f"(x1 * w), "f"(x2 * w), "f"(0.f)
                 : "memory");
}

// warp-per-dst: agg2[d][lane] = sum_e w_e * relu(aggX[s]@W1 + b1)[lane]
// also ws[d][g] accumulated by lanes 0..7
__global__ void __launch_bounds__(256) k_g32f(const float* __restrict__ W1,
                                              const float* __restrict__ b1,
                                              float* __restrict__ agg,
                                              float* __restrict__ ws) {
    int wid = (blockIdx.x * 256 + threadIdx.x) >> 5;
    int lane = threadIdx.x & 31;
    if (wid >= NN) return;
    float wc0 = __ldg(W1 + lane), wc1 = __ldg(W1 + 32 + lane),
          wc2 = __ldg(W1 + 64 + lane), bc = __ldg(b1 + lane);
    int cnt = min(g_cnt[wid], CAP);
    const int2* bk = g_bkt + (size_t)wid * CAP;
    const float4* ax = (const float4*)g_aggX;
    float acc = 0.f, wsacc = 0.f;
    int myg = lane & 7;
    int k = 0;
    for (; k + 4 <= cnt; k += 4) {
        int4 p = *(const int4*)(bk + k);
        int4 q = *(const int4*)(bk + k + 2);
        float4 a0 = __ldg(ax + (p.x & SMASK));
        float4 a1 = __ldg(ax + (p.z & SMASK));
        float4 a2 = __ldg(ax + (q.x & SMASK));
        float4 a3 = __ldg(ax + (q.z & SMASK));
        float w0 = __int_as_float(p.y), w1 = __int_as_float(p.w);
        float w2 = __int_as_float(q.y), w3 = __int_as_float(q.w);
        float h0 = fmaxf(fmaf(a0.x, wc0, fmaf(a0.y, wc1, fmaf(a0.z, wc2, bc))), 0.f);
        float h1 = fmaxf(fmaf(a1.x, wc0, fmaf(a1.y, wc1, fmaf(a1.z, wc2, bc))), 0.f);
        float h2 = fmaxf(fmaf(a2.x, wc0, fmaf(a2.y, wc1, fmaf(a2.z, wc2, bc))), 0.f);
        float h3 = fmaxf(fmaf(a3.x, wc0, fmaf(a3.y, wc1, fmaf(a3.z, wc2, bc))), 0.f);
        acc = fmaf(w0, h0, fmaf(w1, h1, fmaf(w2, h2, fmaf(w3, h3, acc))));
        wsacc += ((p.x >> 20) == myg) ? w0 : 0.f;
        wsacc += ((p.z >> 20) == myg) ? w1 : 0.f;
        wsacc += ((q.x >> 20) == myg) ? w2 : 0.f;
        wsacc += ((q.z >> 20) == myg) ? w3 : 0.f;
    }
    for (; k < cnt; k++) {
        int2 m = bk[k];
        float w = __int_as_float(m.y);
        float4 a = __ldg(ax + (m.x & SMASK));
        float h = fmaxf(fmaf(a.x, wc0, fmaf(a.y, wc1, fmaf(a.z, wc2, bc))), 0.f);
        acc = fmaf(w, h, acc);
        wsacc += ((m.x >> 20) == myg) ? w : 0.f;
    }
    agg[(size_t)wid * 32 + lane] = acc;
    if (lane < 8) ws[wid * NGR + lane] = wsacc;
}

// warp-per-dst gather of h3 (64 features, float2/lane)
__global__ void __launch_bounds__(256) k_g64(const float* __restrict__ t,
                                             float* __restrict__ agg) {
    int wid = (blockIdx.x * 256 + threadIdx.x) >> 5;
    int lane = threadIdx.x & 31;
    if (wid >= NN) return;
    int cnt = min(g_cnt[wid], CAP);
    const int2* bk = g_bkt + (size_t)wid * CAP;
    const float2* tp = (const float2*)t;   // row stride = 32 float2
    float2 acc = make_float2(0.f, 0.f);
    int k = 0;
    for (; k + 4 <= cnt; k += 4) {
        int4 p = *(const int4*)(bk + k);
        int4 q = *(const int4*)(bk + k + 2);
        float2 v0 = __ldg(tp + (size_t)(p.x & SMASK) * 32 + lane);
        float2 v1 = __ldg(tp + (size_t)(p.z & SMASK) * 32 + lane);
        float2 v2 = __ldg(tp + (size_t)(q.x & SMASK) * 32 + lane);
        float2 v3 = __ldg(tp + (size_t)(q.z & SMASK) * 32 + lane);
        float w0 = __int_as_float(p.y), w1 = __int_as_float(p.w);
        float w2 = __int_as_float(q.y), w3 = __int_as_float(q.w);
        acc.x = fmaf(w0, v0.x, acc.x); acc.y = fmaf(w0, v0.y, acc.y);
        acc.x = fmaf(w1, v1.x, acc.x); acc.y = fmaf(w1, v1.y, acc.y);
        acc.x = fmaf(w2, v2.x, acc.x); acc.y = fmaf(w2, v2.y, acc.y);
        acc.x = fmaf(w3, v3.x, acc.x); acc.y = fmaf(w3, v3.y, acc.y);
    }
    for (; k < cnt; k++) {
        int2 m = bk[k];
        float2 v = __ldg(tp + (size_t)(m.x & SMASK) * 32 + lane);
        float w = __int_as_float(m.y);
        acc.x = fmaf(w, v.x, acc.x); acc.y = fmaf(w, v.y, acc.y);
    }
    ((float2*)agg)[(size_t)wid * 32 + lane] = acc;
}

// per node: acc = agg @ W; y = BN(relu(acc + b)); per-graph max-pool into mx
template <int FI>
__global__ void __launch_bounds__(256) k_mm_bn_pool(
        const float* __restrict__ agg, const float* __restrict__ bias,
        const float* __restrict__ W,
        const float* __restrict__ gam, const float* __restrict__ bet,
        const float* __restrict__ mean, const float* __restrict__ var,
        const int* __restrict__ ids, unsigned* __restrict__ mx) {
    constexpr int TPN = FI / 16;
    constexpr int NPB = 256 / TPN;
    __shared__ float sW[FI * FI];
    __shared__ float ssc[FI], ssh[FI], sbv[FI];
    __shared__ unsigned stab[NGR * FI];
    int tid = threadIdx.x;
    for (int k = tid; k < FI * FI; k += 256) sW[k] = W[k];
    if (tid < FI) {
        float sc = gam[tid] * rsqrtf(var[tid] + 1e-3f);
        ssc[tid] = sc;
        ssh[tid] = bet[tid] - mean[tid] * sc;
        sbv[tid] = bias[tid];
    }
    for (int k = tid; k < NGR * FI; k += 256) stab[k] = 0u;
    __syncthreads();

    int i = blockIdx.x * NPB + tid / TPN;
    int coff = (tid % TPN) * 16;
    if (i < NN) {
        const float4* arow = (const float4*)(agg + (size_t)i * FI);
        float acc[16];
#pragma unroll
        for (int c = 0; c < 16; c++) acc[c] = 0.f;
#pragma unroll
        for (int k4 = 0; k4 < FI / 4; k4++) {
            float4 a = arow[k4];
            const float* wr = sW + (k4 * 4) * FI + coff;
#pragma unroll
            for (int c = 0; c < 16; c++) acc[c] = fmaf(a.x, wr[c], acc[c]);
            wr += FI;
#pragma unroll
            for (int c = 0; c < 16; c++) acc[c] = fmaf(a.y, wr[c], acc[c]);
            wr += FI;
#pragma unroll
            for (int c = 0; c < 16; c++) acc[c] = fmaf(a.z, wr[c], acc[c]);
            wr += FI;
#pragma unroll
            for (int c = 0; c < 16; c++) acc[c] = fmaf(a.w, wr[c], acc[c]);
        }
        int g = __ldg(ids + i);
        unsigned* srow = stab + g * FI + coff;
#pragma unroll
        for (int c = 0; c < 16; c++) {
            float hv = fmaxf(acc[c] + sbv[coff + c], 0.f);
            float y = fmaf(hv, ssc[coff + c], ssh[coff + c]);
            atomicMax(srow + c, encf(y));
        }
    }
    __syncthreads();
    for (int k = tid; k < NGR * FI; k += 256) {
        unsigned v = stab[k];
        if (v) atomicMax(mx + k, v);
    }
}

// fused: compute tT3 = pooled1 @ W3 per block (redundant), then
// h3 = relu(ws @ tT3 + b3) for 64 nodes (4 thr/node x 16 cols)
__global__ void __launch_bounds__(256) k_h3f(const float* __restrict__ W3,
                                             const float* __restrict__ b3,
                                             const float* __restrict__ ws,
                                             float* __restrict__ h3) {
    __shared__ float sp[NGR * 32];     // decoded pooled1
    __shared__ float sT[NGR * 64], sb[64];
    int tid = threadIdx.x;
    sp[tid] = decf(g_mx1[tid]);
    if (tid < 64) sb[tid] = b3[tid];
    __syncthreads();
#pragma unroll
    for (int r = 0; r < 2; r++) {
        int idx = tid + r * 256;
        int g = idx >> 6, c = idx & 63;
        float acc = 0.f;
        const float* pr = sp + g * 32;
#pragma unroll
        for (int k = 0; k < 32; k++) acc = fmaf(pr[k], __ldg(W3 + k * 64 + c), acc);
        sT[idx] = acc;
    }
    __syncthreads();

    int i = blockIdx.x * 64 + tid / 4;
    int coff = (tid & 3) * 16;
    if (i >= NN) return;
    const float4* wsr = (const float4*)(ws + i * NGR);
    float4 w0 = wsr[0], w1 = wsr[1];
    float wg[8] = {w0.x, w0.y, w0.z, w0.w, w1.x, w1.y, w1.z, w1.w};
    float acc[16];
#pragma unroll
    for (int c = 0; c < 16; c++) acc[c] = 0.f;
#pragma unroll
    for (int g = 0; g < 8; g++) {
        const float* tr = sT + g * 64 + coff;
#pragma unroll
        for (int c = 0; c < 16; c++) acc[c] = fmaf(wg[g], tr[c], acc[c]);
    }
    float4* to = (float4*)(h3 + (size_t)i * 64 + coff);
#pragma unroll
    for (int c4 = 0; c4 < 4; c4++) {
        float4 r;
#pragma unroll
        for (int u = 0; u < 4; u++)
            ((float*)&r)[u] = fmaxf(acc[c4 * 4 + u] + sb[coff + c4 * 4 + u], 0.f);
        to[c4] = r;
    }
}

// fused: tT5 = pooled2 @ W5 per block, then out = softmax(ws @ tT5 + b5)
__global__ void __launch_bounds__(256) k_outf(const float* __restrict__ W5,
                                              const float* __restrict__ b5,
                                              const float* __restrict__ ws,
                                              float* __restrict__ out) {
    __shared__ float sp[NGR * 64];
    __shared__ float sT[NGR * 20], sb[20];
    int tid = threadIdx.x;
    sp[tid] = decf(g_mx2[tid]);
    sp[tid + 256] = decf(g_mx2[tid + 256]);
    if (tid < 20) sb[tid] = b5[tid];
    __syncthreads();
    if (tid < NGR * 20) {
        int g = tid / 20, c = tid - g * 20;
        float acc = 0.f;
        const float* pr = sp + g * 64;
#pragma unroll
        for (int k = 0; k < 64; k++) acc = fmaf(pr[k], __ldg(W5 + k * 20 + c), acc);
        sT[tid] = acc;
    }
    __syncthreads();

    int i = blockIdx.x * 256 + tid;
    if (i >= NN) return;
    const float4* wsr = (const float4*)(ws + i * NGR);
    float4 w0 = wsr[0], w1 = wsr[1];
    float wg[8] = {w0.x, w0.y, w0.z, w0.w, w1.x, w1.y, w1.z, w1.w};
    float o[20];
#pragma unroll
    for (int c = 0; c < 20; c++) o[c] = sb[c];
#pragma unroll
    for (int g = 0; g < 8; g++) {
        const float* tr = sT + g * 20;
#pragma unroll
        for (int c = 0; c < 20; c++) o[c] = fmaf(wg[g], tr[c], o[c]);
    }
    float mx = -3.4e38f;
#pragma unroll
    for (int c = 0; c < 20; c++) mx = fmaxf(mx, o[c]);
    float s = 0.f;
#pragma unroll
    for (int c = 0; c < 20; c++) { o[c] = __expf(o[c] - mx); s += o[c]; }
    float inv = 1.0f / s;
    float4* to = (float4*)(out + (size_t)i * 20);
#pragma unroll
    for (int c4 = 0; c4 < 5; c4++) {
        float4 r;
#pragma unroll
        for (int u = 0; u < 4; u++) ((float*)&r)[u] = o[c4 * 4 + u] * inv;
        to[c4] = r;
    }
}

// ---------------------------------------------------------------------------
extern "C" void kernel_launch(void* const* d_in, const int* in_sizes, int n_in,
                              void* d_out, int out_size) {
    const float* x   = (const float*)d_in[0];
    const float* ew  = (const float*)d_in[1];
    const int*   src = (const int*)  d_in[2];
    const int*   dst = (const int*)  d_in[3];
    const int*   ids = (const int*)  d_in[4];
    const float* W1  = (const float*)d_in[5];
    const float* b1  = (const float*)d_in[6];
    const float* W2  = (const float*)d_in[7];
    const float* b2  = (const float*)d_in[8];
    const float* g1  = (const float*)d_in[9];
    const float* be1 = (const float*)d_in[10];
    const float* m1  = (const float*)d_in[11];
    const float* v1  = (const float*)d_in[12];
    const float* W3  = (const float*)d_in[13];
    const float* b3  = (const float*)d_in[14];
    const float* W4  = (const float*)d_in[15];
    const float* b4  = (const float*)d_in[16];
    const float* g2  = (const float*)d_in[17];
    const float* be2 = (const float*)d_in[18];
    const float* m2  = (const float*)d_in[19];
    const float* v2  = (const float*)d_in[20];
    const float* W5  = (const float*)d_in[21];
    const float* b5  = (const float*)d_in[22];
    float* out = (float*)d_out;

    float* h3; float* agg; float* ws; unsigned* mx1; unsigned* mx2;
    cudaGetSymbolAddress((void**)&h3,  g_h3);
    cudaGetSymbolAddress((void**)&agg, g_agg);
    cudaGetSymbolAddress((void**)&ws,  g_ws);
    cudaGetSymbolAddress((void**)&mx1, g_mx1);
    cudaGetSymbolAddress((void**)&mx2, g_mx2);

    const int TB = 256;
    const int nblk_node = (NN + TB - 1) / TB;       // 313
    const int nblk_edge = (NE + TB - 1) / TB;       // 5000
    const int nblk_warp = (NN * 32 + TB - 1) / TB;  // 10000

    k_init<<<nblk_node, TB>>>();
    k_fill<<<nblk_edge, TB>>>(src, dst, ew, ids, x);

    // GCN2 aggregate with on-the-fly h1, plus ws histogram
    k_g32f<<<nblk_warp, TB>>>(W1, b1, agg, ws);

    // agg2 @ W2; BN1(relu(+b2)); pool -> mx1
    k_mm_bn_pool<32><<<(NN + 127) / 128, TB>>>(agg, b2, W2, g1, be1, m1, v1, ids, mx1);

    // tT3 (fused) + h3
    k_h3f<<<(NN + 63) / 64, TB>>>(W3, b3, ws, h3);

    // GCN4 aggregate
    k_g64<<<nblk_warp, TB>>>(h3, agg);

    // agg4 @ W4; BN2(relu(+b4)); pool -> mx2
    k_mm_bn_pool<64><<<(NN + 63) / 64, TB>>>(agg, b4, W4, g2, be2, m2, v2, ids, mx2);

    // tT5 (fused) + softmax out
    k_outf<<<nblk_node, TB>>>(W5, b5, ws, out);
}

// round 5
// speedup vs baseline: 11.0136x; 1.2105x over previous
#include <cuda_runtime.h>

#define NN  80000
#define NE  1280000
#define NGR 8
#define CAP 64
#define SMASK 0xFFFFF

// ---- scratch (device globals; no runtime allocation) ----
__device__ float4   g_xp[NN];                // packed (x0,x1,x2, ids-as-float)
__device__ float    g_h3[NN * 64];           // h3 message table
__device__ float4   g_aggX[NN];              // aggregated x (padded to 4)
__device__ float    g_ws[NN * NGR];          // per-dst per-src-graph edge-weight sums
__device__ int      g_cnt[NN];               // per-dst degree
__device__ int2     g_bkt[(size_t)NN * CAP]; // per-dst (src|g<<20, w)
__device__ unsigned g_mx1[NGR * 32];
__device__ unsigned g_mx2[NGR * 64];

__device__ __forceinline__ unsigned encf(float f) {
    unsigned u = __float_as_uint(f);
    return (u & 0x80000000u) ? ~u : (u | 0x80000000u);
}
__device__ __forceinline__ float decf(unsigned u) {
    return __uint_as_float((u & 0x80000000u) ? (u ^ 0x80000000u) : ~u);
}

// ---------------------------------------------------------------------------
// pack xp = (x, ids); zero cnt, aggX, pool tables
__global__ void k_init(const float* __restrict__ x, const int* __restrict__ ids) {
    int i = blockIdx.x * blockDim.x + threadIdx.x;
    if (i < NN) {
        g_cnt[i] = 0;
        g_aggX[i] = make_float4(0.f, 0.f, 0.f, 0.f);
        g_xp[i] = make_float4(__ldg(x + i * 3), __ldg(x + i * 3 + 1), __ldg(x + i * 3 + 2),
                              __int_as_float(__ldg(ids + i)));
    }
    if (i < NGR * 32) g_mx1[i] = 0u;
    if (i < NGR * 64) g_mx2[i] = 0u;
}

// edge-parallel: bucket fill (src|g<<20, w) + aggX[dst] += x[src]*w
__global__ void k_fill(const int* __restrict__ src, const int* __restrict__ dst,
                       const float* __restrict__ ew) {
    int e = blockIdx.x * blockDim.x + threadIdx.x;
    if (e >= NE) return;
    int s = __ldg(src + e), d = __ldg(dst + e);
    float w = __ldg(ew + e);
    float4 xv = __ldg(g_xp + s);
    int g = __float_as_int(xv.w);
    int k = atomicAdd(g_cnt + d, 1);
    if (k < CAP)
        g_bkt[(size_t)d * CAP + k] = make_int2(s | (g << 20), __float_as_int(w));
    float* a = (float*)(g_aggX + d);
    asm volatile("red.global.add.v4.f32 [%0], {%1, %2, %3, %4};"
                 :: "l"(a), "f"(xv.x * w), "f"(xv.y * w), "f"(xv.z * w), "f"(0.f)
                 : "memory");
}

// FUSED GCN1+GCN2+BN1+pool: warp-per-dst.
//  agg2[lane] = sum_e w_e * relu(aggX[s]@W1 + b1)[lane]   (on-the-fly h1)
//  o = agg2 @ W2 (warp shuffle matmul); y = BN(relu(o+b2)); pool max -> mx1
//  ws histogram via lanes 0..7.
__global__ void __launch_bounds__(512) k_gcn2f(
        const float* __restrict__ W1, const float* __restrict__ b1,
        const float* __restrict__ W2, const float* __restrict__ b2,
        const float* __restrict__ g1, const float* __restrict__ be1,
        const float* __restrict__ m1, const float* __restrict__ v1,
        const int* __restrict__ ids,
        float* __restrict__ ws, unsigned* __restrict__ mx) {
    __shared__ float sW2[32 * 32];
    __shared__ unsigned stab[NGR * 32];
    int tid = threadIdx.x;
    for (int k = tid; k < 1024; k += 512) sW2[k] = W2[k];
    if (tid < NGR * 32) stab[tid] = 0u;
    __syncthreads();

    int wid = (blockIdx.x * 512 + tid) >> 5;
    int lane = tid & 31;
    if (wid < NN) {
        float wc0 = __ldg(W1 + lane), wc1 = __ldg(W1 + 32 + lane),
              wc2 = __ldg(W1 + 64 + lane), bc = __ldg(b1 + lane);
        int cnt = min(g_cnt[wid], CAP);
        const int2* bk = g_bkt + (size_t)wid * CAP;
        float acc = 0.f, wsacc = 0.f;
        int myg = lane & 7;
        int k = 0;
        for (; k + 4 <= cnt; k += 4) {
            int4 p = *(const int4*)(bk + k);
            int4 q = *(const int4*)(bk + k + 2);
            float4 a0 = __ldg(g_aggX + (p.x & SMASK));
            float4 a1 = __ldg(g_aggX + (p.z & SMASK));
            float4 a2 = __ldg(g_aggX + (q.x & SMASK));
            float4 a3 = __ldg(g_aggX + (q.z & SMASK));
            float w0 = __int_as_float(p.y), w1 = __int_as_float(p.w);
            float w2 = __int_as_float(q.y), w3 = __int_as_float(q.w);
            float h0 = fmaxf(fmaf(a0.x, wc0, fmaf(a0.y, wc1, fmaf(a0.z, wc2, bc))), 0.f);
            float h1 = fmaxf(fmaf(a1.x, wc0, fmaf(a1.y, wc1, fmaf(a1.z, wc2, bc))), 0.f);
            float h2 = fmaxf(fmaf(a2.x, wc0, fmaf(a2.y, wc1, fmaf(a2.z, wc2, bc))), 0.f);
            float h3 = fmaxf(fmaf(a3.x, wc0, fmaf(a3.y, wc1, fmaf(a3.z, wc2, bc))), 0.f);
            acc = fmaf(w0, h0, fmaf(w1, h1, fmaf(w2, h2, fmaf(w3, h3, acc))));
            wsacc += ((p.x >> 20) == myg) ? w0 : 0.f;
            wsacc += ((p.z >> 20) == myg) ? w1 : 0.f;
            wsacc += ((q.x >> 20) == myg) ? w2 : 0.f;
            wsacc += ((q.z >> 20) == myg) ? w3 : 0.f;
        }
        for (; k < cnt; k++) {
            int2 m = bk[k];
            float w = __int_as_float(m.y);
            float4 a = __ldg(g_aggX + (m.x & SMASK));
            float h = fmaxf(fmaf(a.x, wc0, fmaf(a.y, wc1, fmaf(a.z, wc2, bc))), 0.f);
            acc = fmaf(w, h, acc);
            wsacc += ((m.x >> 20) == myg) ? w : 0.f;
        }
        // agg2 @ W2 via warp shuffles; this lane produces output column `lane`
        float o = 0.f;
#pragma unroll
        for (int kk = 0; kk < 32; kk++) {
            float v = __shfl_sync(0xffffffffu, acc, kk);
            o = fmaf(v, sW2[kk * 32 + lane], o);
        }
        float sc = __ldg(g1 + lane) * rsqrtf(__ldg(v1 + lane) + 1e-3f);
        float sh = __ldg(be1 + lane) - __ldg(m1 + lane) * sc;
        float y = fmaf(fmaxf(o + __ldg(b2 + lane), 0.f), sc, sh);
        int g = __ldg(ids + wid);
        atomicMax(stab + g * 32 + lane, encf(y));
        if (lane < 8) ws[wid * NGR + lane] = wsacc;
    }
    __syncthreads();
    if (tid < NGR * 32) {
        unsigned v = stab[tid];
        if (v) atomicMax(mx + tid, v);
    }
}

// fused: tT3 = pooled1 @ W3 per block (redundant), then
// h3 = relu(ws @ tT3 + b3) for 64 nodes (4 thr/node x 16 cols)
__global__ void __launch_bounds__(256) k_h3f(const float* __restrict__ W3,
                                             const float* __restrict__ b3,
                                             const float* __restrict__ ws,
                                             float* __restrict__ h3) {
    __shared__ float sp[NGR * 32];
    __shared__ float sT[NGR * 64], sb[64];
    int tid = threadIdx.x;
    sp[tid] = decf(g_mx1[tid]);
    if (tid < 64) sb[tid] = b3[tid];
    __syncthreads();
#pragma unroll
    for (int r = 0; r < 2; r++) {
        int idx = tid + r * 256;
        int g = idx >> 6, c = idx & 63;
        float acc = 0.f;
        const float* pr = sp + g * 32;
#pragma unroll
        for (int k = 0; k < 32; k++) acc = fmaf(pr[k], __ldg(W3 + k * 64 + c), acc);
        sT[idx] = acc;
    }
    __syncthreads();

    int i = blockIdx.x * 64 + tid / 4;
    int coff = (tid & 3) * 16;
    if (i >= NN) return;
    const float4* wsr = (const float4*)(ws + i * NGR);
    float4 w0 = wsr[0], w1 = wsr[1];
    float wg[8] = {w0.x, w0.y, w0.z, w0.w, w1.x, w1.y, w1.z, w1.w};
    float acc[16];
#pragma unroll
    for (int c = 0; c < 16; c++) acc[c] = 0.f;
#pragma unroll
    for (int g = 0; g < 8; g++) {
        const float* tr = sT + g * 64 + coff;
#pragma unroll
        for (int c = 0; c < 16; c++) acc[c] = fmaf(wg[g], tr[c], acc[c]);
    }
    float4* to = (float4*)(h3 + (size_t)i * 64 + coff);
#pragma unroll
    for (int c4 = 0; c4 < 4; c4++) {
        float4 r;
#pragma unroll
        for (int u = 0; u < 4; u++)
            ((float*)&r)[u] = fmaxf(acc[c4 * 4 + u] + sb[coff + c4 * 4 + u], 0.f);
        to[c4] = r;
    }
}

// FUSED GCN4+BN2+pool: warp-per-dst, float2/lane (cols 2*lane, 2*lane+1).
__global__ void __launch_bounds__(512) k_gcn4f(
        const float* __restrict__ t,
        const float* __restrict__ W4, const float* __restrict__ b4,
        const float* __restrict__ g2, const float* __restrict__ be2,
        const float* __restrict__ m2, const float* __restrict__ v2,
        const int* __restrict__ ids, unsigned* __restrict__ mx) {
    __shared__ float sW4[64 * 64];
    __shared__ unsigned stab[NGR * 64];
    int tid = threadIdx.x;
    for (int k = tid; k < 4096; k += 512) sW4[k] = W4[k];
    if (tid < NGR * 64) stab[tid] = 0u;
    __syncthreads();

    int wid = (blockIdx.x * 512 + tid) >> 5;
    int lane = tid & 31;
    if (wid < NN) {
        int cnt = min(g_cnt[wid], CAP);
        const int2* bk = g_bkt + (size_t)wid * CAP;
        const float2* tp = (const float2*)t;   // row stride = 32 float2
        float2 acc = make_float2(0.f, 0.f);
        int k = 0;
        for (; k + 4 <= cnt; k += 4) {
            int4 p = *(const int4*)(bk + k);
            int4 q = *(const int4*)(bk + k + 2);
            float2 v0 = __ldg(tp + (size_t)(p.x & SMASK) * 32 + lane);
            float2 v1 = __ldg(tp + (size_t)(p.z & SMASK) * 32 + lane);
            float2 v2l = __ldg(tp + (size_t)(q.x & SMASK) * 32 + lane);
            float2 v3 = __ldg(tp + (size_t)(q.z & SMASK) * 32 + lane);
            float w0 = __int_as_float(p.y), w1 = __int_as_float(p.w);
            float w2 = __int_as_float(q.y), w3 = __int_as_float(q.w);
            acc.x = fmaf(w0, v0.x, acc.x); acc.y = fmaf(w0, v0.y, acc.y);
            acc.x = fmaf(w1, v1.x, acc.x); acc.y = fmaf(w1, v1.y, acc.y);
            acc.x = fmaf(w2, v2l.x, acc.x); acc.y = fmaf(w2, v2l.y, acc.y);
            acc.x = fmaf(w3, v3.x, acc.x); acc.y = fmaf(w3, v3.y, acc.y);
        }
        for (; k < cnt; k++) {
            int2 m = bk[k];
            float2 v = __ldg(tp + (size_t)(m.x & SMASK) * 32 + lane);
            float w = __int_as_float(m.y);
            acc.x = fmaf(w, v.x, acc.x); acc.y = fmaf(w, v.y, acc.y);
        }
        // agg4 @ W4 via warp shuffles; lane owns output cols 2*lane, 2*lane+1
        const float2* sW4_2 = (const float2*)sW4;
        float2 o = make_float2(0.f, 0.f);
#pragma unroll
        for (int j = 0; j < 32; j++) {
            float vx = __shfl_sync(0xffffffffu, acc.x, j);
            float vy = __shfl_sync(0xffffffffu, acc.y, j);
            float2 wr0 = sW4_2[(2 * j) * 32 + lane];
            float2 wr1 = sW4_2[(2 * j + 1) * 32 + lane];
            o.x = fmaf(vx, wr0.x, fmaf(vy, wr1.x, o.x));
            o.y = fmaf(vx, wr0.y, fmaf(vy, wr1.y, o.y));
        }
        float2 bb = __ldg((const float2*)b4 + lane);
        float2 gg = __ldg((const float2*)g2 + lane);
        float2 vv = __ldg((const float2*)v2 + lane);
        float2 mm = __ldg((const float2*)m2 + lane);
        float2 ee = __ldg((const float2*)be2 + lane);
        float sc0 = gg.x * rsqrtf(vv.x + 1e-3f), sc1 = gg.y * rsqrtf(vv.y + 1e-3f);
        float y0 = fmaf(fmaxf(o.x + bb.x, 0.f), sc0, ee.x - mm.x * sc0);
        float y1 = fmaf(fmaxf(o.y + bb.y, 0.f), sc1, ee.y - mm.y * sc1);
        int g = __ldg(ids + wid);
        atomicMax(stab + g * 64 + 2 * lane, encf(y0));
        atomicMax(stab + g * 64 + 2 * lane + 1, encf(y1));
    }
    __syncthreads();
    if (tid < NGR * 64) {
        unsigned v = stab[tid];
        if (v) atomicMax(mx + tid, v);
    }
}

// fused: tT5 = pooled2 @ W5 per block, then out = softmax(ws @ tT5 + b5)
__global__ void __launch_bounds__(256) k_outf(const float* __restrict__ W5,
                                              const float* __restrict__ b5,
                                              const float* __restrict__ ws,
                                              float* __restrict__ out) {
    __shared__ float sp[NGR * 64];
    __shared__ float sT[NGR * 20], sb[20];
    int tid = threadIdx.x;
    sp[tid] = decf(g_mx2[tid]);
    sp[tid + 256] = decf(g_mx2[tid + 256]);
    if (tid < 20) sb[tid] = b5[tid];
    __syncthreads();
    if (tid < NGR * 20) {
        int g = tid / 20, c = tid - g * 20;
        float acc = 0.f;
        const float* pr = sp + g * 64;
#pragma unroll
        for (int k = 0; k < 64; k++) acc = fmaf(pr[k], __ldg(W5 + k * 20 + c), acc);
        sT[tid] = acc;
    }
    __syncthreads();

    int i = blockIdx.x * 256 + tid;
    if (i >= NN) return;
    const float4* wsr = (const float4*)(ws + i * NGR);
    float4 w0 = wsr[0], w1 = wsr[1];
    float wg[8] = {w0.x, w0.y, w0.z, w0.w, w1.x, w1.y, w1.z, w1.w};
    float o[20];
#pragma unroll
    for (int c = 0; c < 20; c++) o[c] = sb[c];
#pragma unroll
    for (int g = 0; g < 8; g++) {
        const float* tr = sT + g * 20;
#pragma unroll
        for (int c = 0; c < 20; c++) o[c] = fmaf(wg[g], tr[c], o[c]);
    }
    float mx = -3.4e38f;
#pragma unroll
    for (int c = 0; c < 20; c++) mx = fmaxf(mx, o[c]);
    float s = 0.f;
#pragma unroll
    for (int c = 0; c < 20; c++) { o[c] = __expf(o[c] - mx); s += o[c]; }
    float inv = 1.0f / s;
    float4* to = (float4*)(out + (size_t)i * 20);
#pragma unroll
    for (int c4 = 0; c4 < 5; c4++) {
        float4 r;
#pragma unroll
        for (int u = 0; u < 4; u++) ((float*)&r)[u] = o[c4 * 4 + u] * inv;
        to[c4] = r;
    }
}

// ---------------------------------------------------------------------------
extern "C" void kernel_launch(void* const* d_in, const int* in_sizes, int n_in,
                              void* d_out, int out_size) {
    const float* x   = (const float*)d_in[0];
    const float* ew  = (const float*)d_in[1];
    const int*   src = (const int*)  d_in[2];
    const int*   dst = (const int*)  d_in[3];
    const int*   ids = (const int*)  d_in[4];
    const float* W1  = (const float*)d_in[5];
    const float* b1  = (const float*)d_in[6];
    const float* W2  = (const float*)d_in[7];
    const float* b2  = (const float*)d_in[8];
    const float* g1  = (const float*)d_in[9];
    const float* be1 = (const float*)d_in[10];
    const float* m1  = (const float*)d_in[11];
    const float* v1  = (const float*)d_in[12];
    const float* W3  = (const float*)d_in[13];
    const float* b3  = (const float*)d_in[14];
    const float* W4  = (const float*)d_in[15];
    const float* b4  = (const float*)d_in[16];
    const float* g2  = (const float*)d_in[17];
    const float* be2 = (const float*)d_in[18];
    const float* m2  = (const float*)d_in[19];
    const float* v2  = (const float*)d_in[20];
    const float* W5  = (const float*)d_in[21];
    const float* b5  = (const float*)d_in[22];
    float* out = (float*)d_out;

    float* h3; float* ws; unsigned* mx1; unsigned* mx2;
    cudaGetSymbolAddress((void**)&h3,  g_h3);
    cudaGetSymbolAddress((void**)&ws,  g_ws);
    cudaGetSymbolAddress((void**)&mx1, g_mx1);
    cudaGetSymbolAddress((void**)&mx2, g_mx2);

    const int TB = 256;
    const int nblk_node = (NN + TB - 1) / TB;        // 313
    const int nblk_edge = (NE + TB - 1) / TB;        // 5000
    const int nblk_w512 = (NN * 32 + 511) / 512;     // 5000

    k_init<<<nblk_node, TB>>>(x, ids);
    k_fill<<<nblk_edge, TB>>>(src, dst, ew);

    // fused GCN1+GCN2+BN1+pool (+ws)
    k_gcn2f<<<nblk_w512, 512>>>(W1, b1, W2, b2, g1, be1, m1, v1, ids, ws, mx1);

    // tT3 (fused) + h3
    k_h3f<<<(NN + 63) / 64, TB>>>(W3, b3, ws, h3);

    // fused GCN4+BN2+pool
    k_gcn4f<<<nblk_w512, 512>>>(h3, W4, b4, g2, be2, m2, v2, ids, mx2);

    // tT5 (fused) + softmax out
    k_outf<<<nblk_node, TB>>>(W5, b5, ws, out);
}